// round 13
// baseline (speedup 1.0000x reference)
#include <cuda_runtime.h>
#include <math.h>
#include <stdint.h>

#define GX 272
#define GY 112
#define GZ 272
#define NCELL 8286208u            /* GX*GY*GZ */
#define NC2   73984u              /* GX*GZ = 289*256 */
#define NROWS 1024
#define NPROP 256
#define RESF  0.03f

#define RPRE  512u                /* rows with precomputed bits */
#define NPREW (RPRE*NC2)          /* 37,879,808 = 8192*4624 */
#define BWORK 8192u               /* counters per bits-block (256 thr * 32) */
#define PB1   1200u               /* bits blocks fused into K1 */
#define PB2   2400u               /* bits blocks fused into K2 */
#define PB3   1024u               /* bits blocks fused into K3 (sum = 4624) */
#define ZBLKS 32368u              /* NCELL/256 float4-zero blocks */
#define CMBLKS 289u               /* NC2/256 */

/* ------------- static device scratch (no allocations) ------------- */
__device__ float4   g_grid4[NCELL];      /* 132 MB: (obj, sx, sy, sz) per cell */
__device__ unsigned g_bits[NPREW];       /* 152 MB: precomputed RNG rows 0..511 */
__device__ float    g_cs[72];
__device__ float    g_dist[NC2];
__device__ float    g_logd[NC2];
__device__ int      g_yidx[NC2];
__device__ unsigned g_bth[NC2];
__device__ float    g_D;
__device__ float    g_world[NROWS*3];
__device__ float    g_scout[NROWS*3];
__device__ int      g_keep[NROWS];

/* ---- pipe-balancing add: IMAD on fma pipe; `one`==1 is a kernel param
   so ptxas cannot strength-reduce it back to IADD3 (alu pipe). Exact. ---- */
__device__ __forceinline__ unsigned addv(unsigned a, unsigned b, unsigned one) {
    unsigned r;
    asm("mad.lo.u32 %0, %1, %2, %3;" : "=r"(r) : "r"(a), "r"(one), "r"(b));
    return r;
}
template<unsigned K>
__device__ __forceinline__ unsigned addk(unsigned a, unsigned one) {
    if constexpr (K == 0u) { return a; }
    else {
        unsigned r;
        asm("mad.lo.u32 %0, %1, %2, %3;" : "=r"(r) : "n"(K), "r"(one), "r"(a));
        return r;
    }
}
/* wide-mul rotate on the fma pipe: rotl(x,r) = lo(x*2^r) | hi(x*2^r);
   the OR fuses with the round xor into one LOP3: (lo|hi)^x0.          */
__device__ __forceinline__ unsigned wrotx(unsigned x, unsigned m, unsigned x0) {
    unsigned long long y = (unsigned long long)x * m;
    return (((unsigned)y) | ((unsigned)(y >> 32))) ^ x0;
}

/* ------------- Threefry-2x32, key=(0,42) -------------
   parity = 0x1BD11BDA  =>  ks2 = 0x1BD11BDA ^ 42 = 0x1BD11BF0
   partitionable mode: ctr = (hi=0, lo=j); 32-bit out = bits1 ^ bits2
   *** bit-exact: integer identities only (assoc. mod-2^32 adds,
       rotate-as-widemul). verified green rounds 6-12 ***              */
/* SHF-form round (alu pipe) */
#define TFR4_S(r) { a0 = addv(a0, a1, one); b0 = addv(b0, b1, one);     \
                    c0 = addv(c0, c1, one); d0 = addv(d0, d1, one);     \
                    a1 = __funnelshift_l(a1, a1, r) ^ a0;               \
                    b1 = __funnelshift_l(b1, b1, r) ^ b0;               \
                    c1 = __funnelshift_l(c1, c1, r) ^ c0;               \
                    d1 = __funnelshift_l(d1, d1, r) ^ d0; }
/* SHF-form round with fused x0-injection: x0 = x0 + K0 + x1 (one IADD3) */
#define TFR4_SI(r, K0) { a0 = a0 + K0 + a1; b0 = b0 + K0 + b1;          \
                    c0 = c0 + K0 + c1; d0 = d0 + K0 + d1;               \
                    a1 = __funnelshift_l(a1, a1, r) ^ a0;               \
                    b1 = __funnelshift_l(b1, b1, r) ^ b0;               \
                    c1 = __funnelshift_l(c1, c1, r) ^ c0;               \
                    d1 = __funnelshift_l(d1, d1, r) ^ d0; }
/* wide-mul-form round (rot on fma pipe) */
#define TFR4_W(m) { a0 = addv(a0, a1, one); b0 = addv(b0, b1, one);     \
                    c0 = addv(c0, c1, one); d0 = addv(d0, d1, one);     \
                    a1 = wrotx(a1, m, a0); b1 = wrotx(b1, m, b0);       \
                    c1 = wrotx(c1, m, c0); d1 = wrotx(d1, m, d0); }
/* wide-mul round with fused x0-injection */
#define TFR4_WI(m, K0) { a0 = a0 + K0 + a1; b0 = b0 + K0 + b1;          \
                    c0 = c0 + K0 + c1; d0 = d0 + K0 + d1;               \
                    a1 = wrotx(a1, m, a0); b1 = wrotx(b1, m, b0);       \
                    c1 = wrotx(c1, m, c0); d1 = wrotx(d1, m, d0); }
/* first round: x0==0 so the add is a copy; rot13 -> wide form */
#define TFR4_FIRST(m) { a0 = a1; b0 = b1; c0 = c1; d0 = d1;             \
                    a1 = wrotx(a1, m, a0); b1 = wrotx(b1, m, b0);       \
                    c1 = wrotx(c1, m, c0); d1 = wrotx(d1, m, d0); }
/* x1-only injection (x0 part fused into the next round or zero) */
#define INJ4X1(K1) { a1 = addk<K1>(a1, one); b1 = addk<K1>(b1, one);    \
                     c1 = addk<K1>(c1, one); d1 = addk<K1>(d1, one); }

__device__ __forceinline__ void tf_bits4(unsigned j0, unsigned j1, unsigned j2, unsigned j3,
                                         unsigned& o0, unsigned& o1, unsigned& o2, unsigned& o3,
                                         unsigned one, unsigned m13, unsigned m15,
                                         unsigned m26, unsigned m6) {
    unsigned a0, a1 = addk<42u>(j0, one);
    unsigned b0, b1 = addk<42u>(j1, one);
    unsigned c0, c1 = addk<42u>(j2, one);
    unsigned d0, d1 = addk<42u>(j3, one);
    /* G1: rounds 1-4 */
    TFR4_FIRST(m13) TFR4_W(m15) TFR4_W(m26) TFR4_W(m6)
    /* inj (42, F1): x1 explicit, x0 fused into next round */
    INJ4X1(0x1BD11BF1u)
    TFR4_SI(17, 42u) TFR4_S(29) TFR4_S(16) TFR4_S(24)
    /* inj (F0, 2) */
    INJ4X1(2u)
    TFR4_WI(m13, 0x1BD11BF0u) TFR4_W(m15) TFR4_W(m26) TFR4_W(m6)
    /* inj (0, 45): x0 untouched */
    INJ4X1(45u)
    TFR4_S(17) TFR4_S(29) TFR4_S(16) TFR4_S(24)
    /* inj (42, F4) */
    INJ4X1(0x1BD11BF4u)
    TFR4_WI(m13, 42u) TFR4_W(m15) TFR4_W(m26) TFR4_S(6)
    /* final inj (F0, 5) feeds the output xor directly */
    o0 = (a0 + 0x1BD11BF0u) ^ (a1 + 5u);
    o1 = (b0 + 0x1BD11BF0u) ^ (b1 + 5u);
    o2 = (c0 + 0x1BD11BF0u) ^ (c1 + 5u);
    o3 = (d0 + 0x1BD11BF0u) ^ (d1 + 5u);
}

/* bits block: 256 threads produce 8192 consecutive counters, coalesced */
__device__ __forceinline__ void bits_job(unsigned blk, unsigned t,
                                         unsigned one, unsigned m13, unsigned m15,
                                         unsigned m26, unsigned m6) {
    unsigned base = blk * BWORK;
    #pragma unroll
    for (unsigned k = 0; k < 32; k += 4) {
        unsigned i0 = base + (k << 8) + t;
        unsigned o0, o1, o2, o3;
        tf_bits4(i0, i0 + 256u, i0 + 512u, i0 + 768u, o0, o1, o2, o3,
                 one, m13, m15, m26, m6);
        g_bits[i0]        = o0;
        g_bits[i0 + 256u] = o1;
        g_bits[i0 + 512u] = o2;
        g_bits[i0 + 768u] = o3;
    }
}

/* ============ K1: bits chunk 1  ||  zero grid  ||  cos/sin table ============ */
__global__ void __launch_bounds__(256) k_f1(unsigned one) {
    unsigned b = blockIdx.x, t = threadIdx.x;
    if (b < PB1) {
        if (b == 0) {
            if (t < 36) {
                float tp  = 6.28318530717958647692f;     /* rounds to f32(2pi) */
                float r36 = __fdiv_rn(1.0f, 36.0f);
                float th  = __fmul_rn(__fmul_rn(tp, (float)t), r36);
                g_cs[2*t]   = cosf(th);
                g_cs[2*t+1] = sinf(th);
            }
            if (t == 0) g_D = 0.0f;
        }
        bits_job(b, t, one, one << 13, one << 15, one << 26, one << 6);
    } else {
        unsigned zb = b - PB1;
        g_grid4[zb*256u + t] = make_float4(0.f, 0.f, 0.f, 0.f);
    }
}

/* ============ K2: Hough vote scatter (v4 red)  ||  bits chunk 2 ============ */
__global__ void __launch_bounds__(256) k_f2(const float* __restrict__ pc,
                                            const float* __restrict__ xyz,
                                            const float* __restrict__ scale,
                                            const float* __restrict__ prob,
                                            const float* __restrict__ corners,
                                            int N, int vb, unsigned one) {
    unsigned b = blockIdx.x, t = threadIdx.x;
    if (b >= (unsigned)vb) {
        bits_job(PB1 + (b - vb), t, one, one << 13, one << 15, one << 26, one << 6);
        return;
    }

    int i = (int)b * 256 + (int)t;
    if (i >= N) return;
    const float RCP = __fdiv_rn(1.0f, RESF);
    float px = pc[3*i], py = pc[3*i+1], pz = pc[3*i+2];
    float ox = xyz[3*i], oy = xyz[3*i+1], oz = xyz[3*i+2];
    float w  = prob[i];
    float c0x = corners[0], c0y = corners[1], c0z = corners[2];

    float ty = __fadd_rn(py, oy);
    float fy = __fadd_rn(__fmul_rn(__fsub_rn(ty, c0y), RCP), 0.5f);
    int iy = (int)floorf(fy);
    if (iy < 0 || iy >= GY) return;          /* zero weight for all rots */

    float wsx = __fmul_rn(w, scale[3*i]);
    float wsy = __fmul_rn(w, scale[3*i+1]);
    float wsz = __fmul_rn(w, scale[3*i+2]);

    #pragma unroll 4
    for (int r = 0; r < 36; r++) {
        float cth = g_cs[2*r], sth = g_cs[2*r+1];
        float rx = __fadd_rn(__fmul_rn(ox, cth), __fmul_rn(oz, sth));
        float rz = __fadd_rn(-__fmul_rn(ox, sth), __fmul_rn(oz, cth));
        float tx = __fadd_rn(px, rx);
        float tz = __fadd_rn(pz, rz);
        int ix = (int)floorf(__fadd_rn(__fmul_rn(__fsub_rn(tx, c0x), RCP), 0.5f));
        int iz = (int)floorf(__fadd_rn(__fmul_rn(__fsub_rn(tz, c0z), RCP), 0.5f));
        if (ix >= 0 && ix < GX && iz >= 0 && iz < GZ) {
            unsigned cell = ((unsigned)(ix*GY + iy))*GZ + (unsigned)iz;
            asm volatile("red.global.add.v4.f32 [%0], {%1, %2, %3, %4};"
                         :: "l"(&g_grid4[cell]), "f"(w), "f"(wsx), "f"(wsy), "f"(wsz)
                         : "memory");
        }
    }
}

/* ============ K3: colmax + dist + sum(dist)  ||  bits chunk 3 ============ */
__global__ void __launch_bounds__(256) k_f3(unsigned one) {
    __shared__ float sh[256];
    unsigned b = blockIdx.x, t = threadIdx.x;
    if (b >= CMBLKS) {
        bits_job(PB1 + PB2 + (b - CMBLKS), t, one, one << 13, one << 15, one << 26, one << 6);
        return;
    }

    unsigned cell = b * 256u + t;                  /* < NC2 exactly */
    unsigned x = cell / GZ, z = cell - x * GZ;
    const float4* col = g_grid4 + (size_t)x * GY * GZ + z;
    float m = col[0].x; int my = 0;
    #pragma unroll 8
    for (int y = 1; y < GY; y++) {
        float v = col[(size_t)y * GZ].x;
        if (v > m) { m = v; my = y; }              /* first index on ties */
    }
    float d = sqrtf(__fadd_rn(m, 1e-7f));          /* XLA pow(x,.5)->sqrt */
    g_dist[cell] = d;
    g_yidx[cell] = my;

    /* block partial sum of dist -> g_D (feeds only the conservative filter) */
    sh[t] = d; __syncthreads();
    for (int o = 128; o > 0; o >>= 1) {
        if (t < (unsigned)o) sh[t] += sh[t + o];
        __syncthreads();
    }
    if (t == 0) atomicAdd(&g_D, sh[0]);
}

/* ============ K4: log(dist) + raw-bits pass threshold (f32) ============
   element can only beat s_T = D/50 if u > T = exp(-50*d_c/D).
   margin 512 mantissa units >> __expf error.                          */
__global__ void __launch_bounds__(256) k_bth() {
    unsigned c = blockIdx.x * 256u + threadIdx.x;
    if (c >= NC2) return;
    float d = g_dist[c];
    g_logd[c] = logf(__fadd_rn(d, 1e-30f));
    float T = __expf(-50.0f * d / g_D);
    int Mi = (int)floorf(T * 8388608.0f) - 512;
    if (Mi < 0) Mi = 0;
    g_bth[c] = ((unsigned)Mi) << 9;
}

/* ============ K5: per-row select + gather + seed dist ============ */
__device__ __forceinline__ void sel_try(unsigned b, unsigned th, int c,
                                        float& bs, int& bi) {
    if (b >= th) {
        unsigned m = b >> 9;
        float u = (m == 0u) ? 1.17549435e-38f
                            : __fadd_rn(__uint_as_float(m | 0x3f800000u), -1.0f);
        float g = -logf(-logf(u));                 /* exact ref gumbel */
        float s = __fadd_rn(g_logd[c], g);
        if (s > bs) { bs = s; bi = c; }
    }
}

__global__ void __launch_bounds__(256, 7) k_sel(const float* __restrict__ corners,
                                                const float* __restrict__ vp, int M,
                                                unsigned one) {
    __shared__ float ss[256];
    __shared__ int   si[256];
    __shared__ float sw[3];
    int r = blockIdx.x, tid = threadIdx.x;
    float bs = -3.4e38f; int bi = 0;
    const uint4* thv = reinterpret_cast<const uint4*>(g_bth);

    if (r < (int)RPRE) {
        /* precomputed rows: stream bits from DRAM, vectorized */
        const uint4* rowb = reinterpret_cast<const uint4*>(g_bits + (size_t)r * NC2);
        for (unsigned q = tid; q < NC2/4u; q += 256u) {
            uint4 v  = rowb[q];
            uint4 th = thv[q];
            int c = (int)(q * 4u);
            sel_try(v.x, th.x, c,   bs, bi);
            sel_try(v.y, th.y, c+1, bs, bi);
            sel_try(v.z, th.z, c+2, bs, bi);
            sel_try(v.w, th.w, c+3, bs, bi);
        }
    } else {
        /* inline threefry rows: 4 counters per iteration (ILP) */
        unsigned m13 = one << 13, m15 = one << 15;
        unsigned m26 = one << 26, m6  = one << 6;
        unsigned base = (unsigned)r * NC2;
        for (unsigned q = tid; q < NC2/4u; q += 256u) {
            unsigned j = base + q * 4u;
            unsigned o0, o1, o2, o3;
            tf_bits4(j, j+1u, j+2u, j+3u, o0, o1, o2, o3, one, m13, m15, m26, m6);
            uint4 th = thv[q];
            int c = (int)(q * 4u);
            sel_try(o0, th.x, c,   bs, bi);
            sel_try(o1, th.y, c+1, bs, bi);
            sel_try(o2, th.z, c+2, bs, bi);
            sel_try(o3, th.w, c+3, bs, bi);
        }
    }

    ss[tid] = bs; si[tid] = bi; __syncthreads();
    for (int o = 128; o > 0; o >>= 1) {
        if (tid < o) {
            float s2 = ss[tid+o]; int i2 = si[tid+o];
            if (s2 > ss[tid] || (s2 == ss[tid] && i2 < si[tid])) { ss[tid] = s2; si[tid] = i2; }
        }
        __syncthreads();
    }

    if (tid == 0) {
        int c  = si[0];
        int xi = c / GZ, zi = c - (c / GZ) * GZ;
        int yi = g_yidx[c];
        float wx = __fadd_rn(__fmul_rn((float)xi, RESF), corners[0]);
        float wy = __fadd_rn(__fmul_rn((float)yi, RESF), corners[1]);
        float wz = __fadd_rn(__fmul_rn((float)zi, RESF), corners[2]);
        g_world[3*r+0] = wx; g_world[3*r+1] = wy; g_world[3*r+2] = wz;
        sw[0] = wx; sw[1] = wy; sw[2] = wz;
        unsigned cell = ((unsigned)(xi*GY + yi))*GZ + (unsigned)zi;
        float4 gv = g_grid4[cell];
        float den = __fadd_rn(gv.x, 1e-7f);
        g_scout[3*r+0] = __fdiv_rn(gv.y, den);
        g_scout[3*r+1] = __fdiv_rn(gv.z, den);
        g_scout[3*r+2] = __fdiv_rn(gv.w, den);
    }
    __syncthreads();

    /* min distance to seed points for this row */
    float wx = sw[0], wy = sw[1], wz = sw[2];
    float mind = 3.4e38f;
    for (int m = tid; m < M; m += 256) {
        float dx = __fsub_rn(wx, vp[3*m]);
        float dy = __fsub_rn(wy, vp[3*m+1]);
        float dz = __fsub_rn(wz, vp[3*m+2]);
        float s  = __fadd_rn(__fadd_rn(__fmul_rn(dx,dx), __fmul_rn(dy,dy)), __fmul_rn(dz,dz));
        mind = fminf(mind, sqrtf(s));
    }
    ss[tid] = mind; __syncthreads();
    for (int o = 128; o > 0; o >>= 1) {
        if (tid < o) ss[tid] = fminf(ss[tid], ss[tid+o]);
        __syncthreads();
    }
    if (tid == 0) g_keep[r] = (ss[0] < 0.3f) ? 1 : 0;
}

/* ============ K6: parallel stable selection + output write ============ */
__global__ void __launch_bounds__(1024) k_finish(float* __restrict__ out) {
    __shared__ int sk[NROWS];
    int t = threadIdx.x;                       /* 1024 threads, one per row */
    int kp = g_keep[t];
    sk[t] = kp; __syncthreads();

    /* inclusive prefix sum of keep flags (Hillis-Steele) */
    for (int o = 1; o < NROWS; o <<= 1) {
        int val = sk[t];
        if (t >= o) val += sk[t - o];
        __syncthreads();
        sk[t] = val;
        __syncthreads();
    }
    int incl  = sk[t];
    int total = sk[NROWS - 1];

    /* output slot for this row under stable argsort(where(keep,0,1)) */
    int slot;
    if (total > 0) slot = kp ? (incl - 1) : (total + (t - incl));
    else           slot = t;                   /* keep.any()==False -> identity */

    if (slot < NPROP) {
        out[3*slot+0] = g_world[3*t+0];
        out[3*slot+1] = g_world[3*t+1];
        out[3*slot+2] = g_world[3*t+2];
        out[4*NPROP + 3*slot+0] = g_scout[3*t+0];
        out[4*NPROP + 3*slot+1] = g_scout[3*t+1];
        out[4*NPROP + 3*slot+2] = g_scout[3*t+2];
    }
    if (t < NPROP) out[3*NPROP + t] = 0.0f;    /* probs = zeros */
}

extern "C" void kernel_launch(void* const* d_in, const int* in_sizes, int n_in,
                              void* d_out, int out_size) {
    const float* pc      = (const float*)d_in[0];
    const float* xyz     = (const float*)d_in[1];
    const float* scale   = (const float*)d_in[2];
    const float* prob    = (const float*)d_in[3];
    const float* corners = (const float*)d_in[4];
    const float* vp      = (const float*)d_in[5];
    int N = in_sizes[0] / 3;
    int M = in_sizes[5] / 3;
    float* out = (float*)d_out;
    int vb = (N + 255) / 256;
    unsigned one = 1u;                          /* opaque to ptxas: pipe-balancing anchor */

    k_f1<<<PB1 + ZBLKS, 256>>>(one);
    k_f2<<<vb + PB2, 256>>>(pc, xyz, scale, prob, corners, N, vb, one);
    k_f3<<<CMBLKS + PB3, 256>>>(one);
    k_bth<<<CMBLKS, 256>>>();
    k_sel<<<NROWS, 256>>>(corners, vp, M, one);
    k_finish<<<1, 1024>>>(out);
}

// round 14
// speedup vs baseline: 1.0535x; 1.0535x over previous
#include <cuda_runtime.h>
#include <math.h>
#include <stdint.h>

#define GX 272
#define GY 112
#define GZ 272
#define NCELL 8286208u            /* GX*GY*GZ */
#define NC2   73984u              /* GX*GZ = 289*256 */
#define NROWS 1024
#define NPROP 256
#define RESF  0.03f

#define RPRE  512u                /* rows with precomputed bits */
#define NPREW (RPRE*NC2)          /* 37,879,808 = 8192*4624 */
#define BWORK 8192u               /* counters per bits-block (256 thr * 32) */
#define PB1   1200u               /* bits blocks fused into K1 */
#define PB2   2400u               /* bits blocks fused into K2 */
#define PB3   1024u               /* bits blocks fused into K3 (sum = 4624) */
#define ZBLKS 32368u              /* NCELL/256 float4-zero blocks */
#define CMBLKS 289u               /* NC2/256 */

/* ------------- static device scratch (no allocations) ------------- */
__device__ float4   g_grid4[NCELL];      /* 132 MB: (obj, sx, sy, sz) per cell */
__device__ unsigned g_bits[NPREW];       /* 152 MB: precomputed RNG rows 0..511 */
__device__ float    g_cs[72];
__device__ float    g_dist[NC2];
__device__ float    g_logd[NC2];
__device__ int      g_yidx[NC2];
__device__ unsigned g_bth[NC2];
__device__ float    g_D;
__device__ float    g_world[NROWS*3];
__device__ float    g_scout[NROWS*3];
__device__ int      g_keep[NROWS];

/* ---- pipe-balancing add: IMAD on fma pipe; `one`==1 is a kernel param
   so ptxas cannot strength-reduce it back to IADD3 (alu pipe). Exact. ---- */
__device__ __forceinline__ unsigned addv(unsigned a, unsigned b, unsigned one) {
    unsigned r;
    asm("mad.lo.u32 %0, %1, %2, %3;" : "=r"(r) : "r"(a), "r"(one), "r"(b));
    return r;
}
template<unsigned K>
__device__ __forceinline__ unsigned addk(unsigned a, unsigned one) {
    if constexpr (K == 0u) { return a; }
    else {
        unsigned r;
        asm("mad.lo.u32 %0, %1, %2, %3;" : "=r"(r) : "n"(K), "r"(one), "r"(a));
        return r;
    }
}
/* wide-mul rotate on the fma pipe: rotl(x,r) = lo(x*2^r) | hi(x*2^r);
   the OR fuses with the round xor into one LOP3: (lo|hi)^x0.
   NOTE (round-13 lesson): at most 6 of these per eval — more overloads
   the fma pipe / register budget and regresses.                       */
__device__ __forceinline__ unsigned wrotx(unsigned x, unsigned m, unsigned x0) {
    unsigned long long y = (unsigned long long)x * m;
    return (((unsigned)y) | ((unsigned)(y >> 32))) ^ x0;
}

/* ------------- Threefry-2x32, key=(0,42) -------------
   parity = 0x1BD11BDA  =>  ks2 = 0x1BD11BDA ^ 42 = 0x1BD11BF0
   partitionable mode: ctr = (hi=0, lo=j); 32-bit out = bits1 ^ bits2
   *** verified bit-exact rounds 6-13 — integer identities only ***    */
/* SHF-form round (alu pipe) */
#define TFR4_S(r) { a0 = addv(a0, a1, one); b0 = addv(b0, b1, one);     \
                    c0 = addv(c0, c1, one); d0 = addv(d0, d1, one);     \
                    a1 = __funnelshift_l(a1, a1, r) ^ a0;               \
                    b1 = __funnelshift_l(b1, b1, r) ^ b0;               \
                    c1 = __funnelshift_l(c1, c1, r) ^ c0;               \
                    d1 = __funnelshift_l(d1, d1, r) ^ d0; }
/* wide-mul-form round (rot on fma pipe) */
#define TFR4_W(m) { a0 = addv(a0, a1, one); b0 = addv(b0, b1, one);     \
                    c0 = addv(c0, c1, one); d0 = addv(d0, d1, one);     \
                    a1 = wrotx(a1, m, a0); b1 = wrotx(b1, m, b0);       \
                    c1 = wrotx(c1, m, c0); d1 = wrotx(d1, m, d0); }
/* first round: x0==0 so the add is a copy; rot13 -> wide form */
#define TFR4_FIRST(m) { a0 = a1; b0 = b1; c0 = c1; d0 = d1;             \
                    a1 = wrotx(a1, m, a0); b1 = wrotx(b1, m, b0);       \
                    c1 = wrotx(c1, m, c0); d1 = wrotx(d1, m, d0); }
#define INJ4K(K0, K1) { a0 = addk<K0>(a0, one); b0 = addk<K0>(b0, one); \
                        c0 = addk<K0>(c0, one); d0 = addk<K0>(d0, one); \
                        a1 = addk<K1>(a1, one); b1 = addk<K1>(b1, one); \
                        c1 = addk<K1>(c1, one); d1 = addk<K1>(d1, one); }

__device__ __forceinline__ void tf_bits4(unsigned j0, unsigned j1, unsigned j2, unsigned j3,
                                         unsigned& o0, unsigned& o1, unsigned& o2, unsigned& o3,
                                         unsigned one, unsigned m13, unsigned m15) {
    unsigned a0, a1 = addk<42u>(j0, one);
    unsigned b0, b1 = addk<42u>(j1, one);
    unsigned c0, c1 = addk<42u>(j2, one);
    unsigned d0, d1 = addk<42u>(j3, one);
    TFR4_FIRST(m13) TFR4_W(m15) TFR4_S(26) TFR4_S(6)
    INJ4K(42u, 0x1BD11BF1u)
    TFR4_S(17) TFR4_S(29) TFR4_S(16) TFR4_S(24)
    INJ4K(0x1BD11BF0u, 2u)
    TFR4_W(m13) TFR4_W(m15) TFR4_S(26) TFR4_S(6)
    INJ4K(0u, 45u)
    TFR4_S(17) TFR4_S(29) TFR4_S(16) TFR4_S(24)
    INJ4K(42u, 0x1BD11BF4u)
    TFR4_W(m13) TFR4_W(m15) TFR4_S(26) TFR4_S(6)
    INJ4K(0x1BD11BF0u, 5u)
    o0 = a0 ^ a1; o1 = b0 ^ b1; o2 = c0 ^ c1; o3 = d0 ^ d1;
}

/* bits block: 256 threads produce 8192 consecutive counters, coalesced */
__device__ __forceinline__ void bits_job(unsigned blk, unsigned t,
                                         unsigned one, unsigned m13, unsigned m15) {
    unsigned base = blk * BWORK;
    #pragma unroll
    for (unsigned k = 0; k < 32; k += 4) {
        unsigned i0 = base + (k << 8) + t;
        unsigned o0, o1, o2, o3;
        tf_bits4(i0, i0 + 256u, i0 + 512u, i0 + 768u, o0, o1, o2, o3, one, m13, m15);
        g_bits[i0]        = o0;
        g_bits[i0 + 256u] = o1;
        g_bits[i0 + 512u] = o2;
        g_bits[i0 + 768u] = o3;
    }
}

/* ============ K1: bits chunk 1  ||  zero grid  ||  cos/sin table ============ */
__global__ void __launch_bounds__(256) k_f1(unsigned one) {
    unsigned b = blockIdx.x, t = threadIdx.x;
    if (b < PB1) {
        if (b == 0) {
            if (t < 36) {
                float tp  = 6.28318530717958647692f;     /* rounds to f32(2pi) */
                float r36 = __fdiv_rn(1.0f, 36.0f);
                float th  = __fmul_rn(__fmul_rn(tp, (float)t), r36);
                g_cs[2*t]   = cosf(th);
                g_cs[2*t+1] = sinf(th);
            }
            if (t == 0) g_D = 0.0f;
        }
        bits_job(b, t, one, one << 13, one << 15);
    } else {
        unsigned zb = b - PB1;
        g_grid4[zb*256u + t] = make_float4(0.f, 0.f, 0.f, 0.f);
    }
}

/* ============ K2: Hough vote scatter (v4 red)  ||  bits chunk 2 ============ */
__global__ void __launch_bounds__(256) k_f2(const float* __restrict__ pc,
                                            const float* __restrict__ xyz,
                                            const float* __restrict__ scale,
                                            const float* __restrict__ prob,
                                            const float* __restrict__ corners,
                                            int N, int vb, unsigned one) {
    unsigned b = blockIdx.x, t = threadIdx.x;
    if (b >= (unsigned)vb) { bits_job(PB1 + (b - vb), t, one, one << 13, one << 15); return; }

    int i = (int)b * 256 + (int)t;
    if (i >= N) return;
    const float RCP = __fdiv_rn(1.0f, RESF);
    float px = pc[3*i], py = pc[3*i+1], pz = pc[3*i+2];
    float ox = xyz[3*i], oy = xyz[3*i+1], oz = xyz[3*i+2];
    float w  = prob[i];
    float c0x = corners[0], c0y = corners[1], c0z = corners[2];

    float ty = __fadd_rn(py, oy);
    float fy = __fadd_rn(__fmul_rn(__fsub_rn(ty, c0y), RCP), 0.5f);
    int iy = (int)floorf(fy);
    if (iy < 0 || iy >= GY) return;          /* zero weight for all rots */

    float wsx = __fmul_rn(w, scale[3*i]);
    float wsy = __fmul_rn(w, scale[3*i+1]);
    float wsz = __fmul_rn(w, scale[3*i+2]);

    #pragma unroll 4
    for (int r = 0; r < 36; r++) {
        float cth = g_cs[2*r], sth = g_cs[2*r+1];
        float rx = __fadd_rn(__fmul_rn(ox, cth), __fmul_rn(oz, sth));
        float rz = __fadd_rn(-__fmul_rn(ox, sth), __fmul_rn(oz, cth));
        float tx = __fadd_rn(px, rx);
        float tz = __fadd_rn(pz, rz);
        int ix = (int)floorf(__fadd_rn(__fmul_rn(__fsub_rn(tx, c0x), RCP), 0.5f));
        int iz = (int)floorf(__fadd_rn(__fmul_rn(__fsub_rn(tz, c0z), RCP), 0.5f));
        if (ix >= 0 && ix < GX && iz >= 0 && iz < GZ) {
            unsigned cell = ((unsigned)(ix*GY + iy))*GZ + (unsigned)iz;
            asm volatile("red.global.add.v4.f32 [%0], {%1, %2, %3, %4};"
                         :: "l"(&g_grid4[cell]), "f"(w), "f"(wsx), "f"(wsy), "f"(wsz)
                         : "memory");
        }
    }
}

/* ============ K3: colmax + dist + sum(dist)  ||  bits chunk 3 ============ */
__global__ void __launch_bounds__(256) k_f3(unsigned one) {
    __shared__ float sh[256];
    unsigned b = blockIdx.x, t = threadIdx.x;
    if (b >= CMBLKS) { bits_job(PB1 + PB2 + (b - CMBLKS), t, one, one << 13, one << 15); return; }

    unsigned cell = b * 256u + t;                  /* < NC2 exactly */
    unsigned x = cell / GZ, z = cell - x * GZ;
    const float4* col = g_grid4 + (size_t)x * GY * GZ + z;
    float m = col[0].x; int my = 0;
    #pragma unroll 8
    for (int y = 1; y < GY; y++) {
        float v = col[(size_t)y * GZ].x;
        if (v > m) { m = v; my = y; }              /* first index on ties */
    }
    float d = sqrtf(__fadd_rn(m, 1e-7f));          /* XLA pow(x,.5)->sqrt */
    g_dist[cell] = d;
    g_yidx[cell] = my;

    /* block partial sum of dist -> g_D (feeds only the conservative filter) */
    sh[t] = d; __syncthreads();
    for (int o = 128; o > 0; o >>= 1) {
        if (t < (unsigned)o) sh[t] += sh[t + o];
        __syncthreads();
    }
    if (t == 0) atomicAdd(&g_D, sh[0]);
}

/* ============ K4: log(dist) + raw-bits pass threshold (f32) ============
   element can only beat s_T = D/50 if u > T = exp(-50*d_c/D).
   margin 512 mantissa units >> __expf error.                          */
__global__ void __launch_bounds__(256) k_bth() {
    unsigned c = blockIdx.x * 256u + threadIdx.x;
    if (c >= NC2) return;
    float d = g_dist[c];
    g_logd[c] = logf(__fadd_rn(d, 1e-30f));
    float T = __expf(-50.0f * d / g_D);
    int Mi = (int)floorf(T * 8388608.0f) - 512;
    if (Mi < 0) Mi = 0;
    g_bth[c] = ((unsigned)Mi) << 9;
}

/* ============ K5: per-row select + gather + seed dist ============ */
__device__ __forceinline__ void sel_try(unsigned b, unsigned th, int c,
                                        float& bs, int& bi) {
    if (b >= th) {
        unsigned m = b >> 9;
        float u = (m == 0u) ? 1.17549435e-38f
                            : __fadd_rn(__uint_as_float(m | 0x3f800000u), -1.0f);
        float g = -logf(-logf(u));                 /* exact ref gumbel */
        float s = __fadd_rn(g_logd[c], g);
        if (s > bs) { bs = s; bi = c; }
    }
}

__global__ void __launch_bounds__(256, 7) k_sel(const float* __restrict__ corners,
                                                const float* __restrict__ vp, int M,
                                                unsigned one) {
    __shared__ float ss[256];
    __shared__ int   si[256];
    __shared__ float sw[3];
    int r = blockIdx.x, tid = threadIdx.x;
    float bs = -3.4e38f; int bi = 0;
    const uint4* thv = reinterpret_cast<const uint4*>(g_bth);

    if (r < (int)RPRE) {
        /* precomputed rows: stream bits from DRAM, vectorized */
        const uint4* rowb = reinterpret_cast<const uint4*>(g_bits + (size_t)r * NC2);
        for (unsigned q = tid; q < NC2/4u; q += 256u) {
            uint4 v  = rowb[q];
            uint4 th = thv[q];
            int c = (int)(q * 4u);
            sel_try(v.x, th.x, c,   bs, bi);
            sel_try(v.y, th.y, c+1, bs, bi);
            sel_try(v.z, th.z, c+2, bs, bi);
            sel_try(v.w, th.w, c+3, bs, bi);
        }
    } else {
        /* inline threefry rows: 4 counters per iteration (ILP) */
        unsigned m13 = one << 13, m15 = one << 15;
        unsigned base = (unsigned)r * NC2;
        for (unsigned q = tid; q < NC2/4u; q += 256u) {
            unsigned j = base + q * 4u;
            unsigned o0, o1, o2, o3;
            tf_bits4(j, j+1u, j+2u, j+3u, o0, o1, o2, o3, one, m13, m15);
            uint4 th = thv[q];
            int c = (int)(q * 4u);
            sel_try(o0, th.x, c,   bs, bi);
            sel_try(o1, th.y, c+1, bs, bi);
            sel_try(o2, th.z, c+2, bs, bi);
            sel_try(o3, th.w, c+3, bs, bi);
        }
    }

    ss[tid] = bs; si[tid] = bi; __syncthreads();
    for (int o = 128; o > 0; o >>= 1) {
        if (tid < o) {
            float s2 = ss[tid+o]; int i2 = si[tid+o];
            if (s2 > ss[tid] || (s2 == ss[tid] && i2 < si[tid])) { ss[tid] = s2; si[tid] = i2; }
        }
        __syncthreads();
    }

    if (tid == 0) {
        int c  = si[0];
        int xi = c / GZ, zi = c - (c / GZ) * GZ;
        int yi = g_yidx[c];
        float wx = __fadd_rn(__fmul_rn((float)xi, RESF), corners[0]);
        float wy = __fadd_rn(__fmul_rn((float)yi, RESF), corners[1]);
        float wz = __fadd_rn(__fmul_rn((float)zi, RESF), corners[2]);
        g_world[3*r+0] = wx; g_world[3*r+1] = wy; g_world[3*r+2] = wz;
        sw[0] = wx; sw[1] = wy; sw[2] = wz;
        unsigned cell = ((unsigned)(xi*GY + yi))*GZ + (unsigned)zi;
        float4 gv = g_grid4[cell];
        float den = __fadd_rn(gv.x, 1e-7f);
        g_scout[3*r+0] = __fdiv_rn(gv.y, den);
        g_scout[3*r+1] = __fdiv_rn(gv.z, den);
        g_scout[3*r+2] = __fdiv_rn(gv.w, den);
    }
    __syncthreads();

    /* min distance to seed points for this row */
    float wx = sw[0], wy = sw[1], wz = sw[2];
    float mind = 3.4e38f;
    for (int m = tid; m < M; m += 256) {
        float dx = __fsub_rn(wx, vp[3*m]);
        float dy = __fsub_rn(wy, vp[3*m+1]);
        float dz = __fsub_rn(wz, vp[3*m+2]);
        float s  = __fadd_rn(__fadd_rn(__fmul_rn(dx,dx), __fmul_rn(dy,dy)), __fmul_rn(dz,dz));
        mind = fminf(mind, sqrtf(s));
    }
    ss[tid] = mind; __syncthreads();
    for (int o = 128; o > 0; o >>= 1) {
        if (tid < o) ss[tid] = fminf(ss[tid], ss[tid+o]);
        __syncthreads();
    }
    if (tid == 0) g_keep[r] = (ss[0] < 0.3f) ? 1 : 0;
}

/* ============ K6: parallel stable selection + output write ============ */
__global__ void __launch_bounds__(1024) k_finish(float* __restrict__ out) {
    __shared__ int sk[NROWS];
    int t = threadIdx.x;                       /* 1024 threads, one per row */
    int kp = g_keep[t];
    sk[t] = kp; __syncthreads();

    /* inclusive prefix sum of keep flags (Hillis-Steele) */
    for (int o = 1; o < NROWS; o <<= 1) {
        int val = sk[t];
        if (t >= o) val += sk[t - o];
        __syncthreads();
        sk[t] = val;
        __syncthreads();
    }
    int incl  = sk[t];
    int total = sk[NROWS - 1];

    /* output slot for this row under stable argsort(where(keep,0,1)) */
    int slot;
    if (total > 0) slot = kp ? (incl - 1) : (total + (t - incl));
    else           slot = t;                   /* keep.any()==False -> identity */

    if (slot < NPROP) {
        out[3*slot+0] = g_world[3*t+0];
        out[3*slot+1] = g_world[3*t+1];
        out[3*slot+2] = g_world[3*t+2];
        out[4*NPROP + 3*slot+0] = g_scout[3*t+0];
        out[4*NPROP + 3*slot+1] = g_scout[3*t+1];
        out[4*NPROP + 3*slot+2] = g_scout[3*t+2];
    }
    if (t < NPROP) out[3*NPROP + t] = 0.0f;    /* probs = zeros */
}

extern "C" void kernel_launch(void* const* d_in, const int* in_sizes, int n_in,
                              void* d_out, int out_size) {
    const float* pc      = (const float*)d_in[0];
    const float* xyz     = (const float*)d_in[1];
    const float* scale   = (const float*)d_in[2];
    const float* prob    = (const float*)d_in[3];
    const float* corners = (const float*)d_in[4];
    const float* vp      = (const float*)d_in[5];
    int N = in_sizes[0] / 3;
    int M = in_sizes[5] / 3;
    float* out = (float*)d_out;
    int vb = (N + 255) / 256;
    unsigned one = 1u;                          /* opaque to ptxas: pipe-balancing anchor */

    k_f1<<<PB1 + ZBLKS, 256>>>(one);
    k_f2<<<vb + PB2, 256>>>(pc, xyz, scale, prob, corners, N, vb, one);
    k_f3<<<CMBLKS + PB3, 256>>>(one);
    k_bth<<<CMBLKS, 256>>>();
    k_sel<<<NROWS, 256>>>(corners, vp, M, one);
    k_finish<<<1, 1024>>>(out);
}

// round 16
// speedup vs baseline: 1.0804x; 1.0255x over previous
#include <cuda_runtime.h>
#include <math.h>
#include <stdint.h>

#define GX 272
#define GY 112
#define GZ 272
#define NCELL 8286208u            /* GX*GY*GZ */
#define NC2   73984u              /* GX*GZ = 289*256 */
#define NROWS 1024
#define NPROP 256
#define RESF  0.03f

#define RPRE  768u                /* rows with precomputed bits */
#define NPREW (RPRE*NC2)          /* 56,819,712 = 8192*6936 */
#define BWORK 8192u               /* counters per bits-block (256 thr * 32) */
#define PB1   1200u               /* bits blocks fused into K1 */
#define PB2   4712u               /* bits blocks fused into K2 (under vote's atomic drain) */
#define PB3   1024u               /* bits blocks fused into K3 (sum = 6936) */
#define ZFAT  2023u               /* fat zero blocks: 2023*4096 float4 = NCELL */
#define CMBLKS 289u               /* NC2/256 */

/* ------------- static device scratch (no allocations) ------------- */
__device__ float4   g_grid4[NCELL];      /* 132 MB: (obj, sx, sy, sz) per cell */
__device__ unsigned g_bits[NPREW];       /* 227 MB: precomputed RNG rows 0..767 */
__device__ float    g_cs[72];
__device__ float    g_dist[NC2];
__device__ float    g_logd[NC2];
__device__ int      g_yidx[NC2];
__device__ unsigned g_bth[NC2];
__device__ float    g_D;
__device__ float    g_world[NROWS*3];
__device__ float    g_scout[NROWS*3];
__device__ int      g_keep[NROWS];

/* ---- pipe-balancing add: IMAD on fma pipe; `one`==1 is a kernel param
   so ptxas cannot strength-reduce it back to IADD3 (alu pipe). Exact. ---- */
__device__ __forceinline__ unsigned addv(unsigned a, unsigned b, unsigned one) {
    unsigned r;
    asm("mad.lo.u32 %0, %1, %2, %3;" : "=r"(r) : "r"(a), "r"(one), "r"(b));
    return r;
}
template<unsigned K>
__device__ __forceinline__ unsigned addk(unsigned a, unsigned one) {
    if constexpr (K == 0u) { return a; }
    else {
        unsigned r;
        asm("mad.lo.u32 %0, %1, %2, %3;" : "=r"(r) : "n"(K), "r"(one), "r"(a));
        return r;
    }
}
/* wide-mul rotate on the fma pipe: rotl(x,r) = lo(x*2^r) | hi(x*2^r);
   the OR fuses with the round xor into one LOP3: (lo|hi)^x0.
   NOTE (round-13 lesson): at most 6 of these per eval — more overloads
   the fma pipe / register budget and regresses.                       */
__device__ __forceinline__ unsigned wrotx(unsigned x, unsigned m, unsigned x0) {
    unsigned long long y = (unsigned long long)x * m;
    return (((unsigned)y) | ((unsigned)(y >> 32))) ^ x0;
}

/* ------------- Threefry-2x32, key=(0,42) -------------
   parity = 0x1BD11BDA  =>  ks2 = 0x1BD11BDA ^ 42 = 0x1BD11BF0
   partitionable mode: ctr = (hi=0, lo=j); 32-bit out = bits1 ^ bits2
   *** verified bit-exact rounds 6-14 — integer identities only ***    */
/* SHF-form round (alu pipe) */
#define TFR4_S(r) { a0 = addv(a0, a1, one); b0 = addv(b0, b1, one);     \
                    c0 = addv(c0, c1, one); d0 = addv(d0, d1, one);     \
                    a1 = __funnelshift_l(a1, a1, r) ^ a0;               \
                    b1 = __funnelshift_l(b1, b1, r) ^ b0;               \
                    c1 = __funnelshift_l(c1, c1, r) ^ c0;               \
                    d1 = __funnelshift_l(d1, d1, r) ^ d0; }
/* wide-mul-form round (rot on fma pipe) */
#define TFR4_W(m) { a0 = addv(a0, a1, one); b0 = addv(b0, b1, one);     \
                    c0 = addv(c0, c1, one); d0 = addv(d0, d1, one);     \
                    a1 = wrotx(a1, m, a0); b1 = wrotx(b1, m, b0);       \
                    c1 = wrotx(c1, m, c0); d1 = wrotx(d1, m, d0); }
/* first round: x0==0 so the add is a copy; rot13 -> wide form */
#define TFR4_FIRST(m) { a0 = a1; b0 = b1; c0 = c1; d0 = d1;             \
                    a1 = wrotx(a1, m, a0); b1 = wrotx(b1, m, b0);       \
                    c1 = wrotx(c1, m, c0); d1 = wrotx(d1, m, d0); }
#define INJ4K(K0, K1) { a0 = addk<K0>(a0, one); b0 = addk<K0>(b0, one); \
                        c0 = addk<K0>(c0, one); d0 = addk<K0>(d0, one); \
                        a1 = addk<K1>(a1, one); b1 = addk<K1>(b1, one); \
                        c1 = addk<K1>(c1, one); d1 = addk<K1>(d1, one); }

__device__ __forceinline__ void tf_bits4(unsigned j0, unsigned j1, unsigned j2, unsigned j3,
                                         unsigned& o0, unsigned& o1, unsigned& o2, unsigned& o3,
                                         unsigned one, unsigned m13, unsigned m15) {
    unsigned a0, a1 = addk<42u>(j0, one);
    unsigned b0, b1 = addk<42u>(j1, one);
    unsigned c0, c1 = addk<42u>(j2, one);
    unsigned d0, d1 = addk<42u>(j3, one);
    TFR4_FIRST(m13) TFR4_W(m15) TFR4_S(26) TFR4_S(6)
    INJ4K(42u, 0x1BD11BF1u)
    TFR4_S(17) TFR4_S(29) TFR4_S(16) TFR4_S(24)
    INJ4K(0x1BD11BF0u, 2u)
    TFR4_W(m13) TFR4_W(m15) TFR4_S(26) TFR4_S(6)
    INJ4K(0u, 45u)
    TFR4_S(17) TFR4_S(29) TFR4_S(16) TFR4_S(24)
    INJ4K(42u, 0x1BD11BF4u)
    TFR4_W(m13) TFR4_W(m15) TFR4_S(26) TFR4_S(6)
    INJ4K(0x1BD11BF0u, 5u)
    o0 = a0 ^ a1; o1 = b0 ^ b1; o2 = c0 ^ c1; o3 = d0 ^ d1;
}

/* bits block: 256 threads produce 8192 consecutive counters, coalesced */
__device__ __forceinline__ void bits_job(unsigned blk, unsigned t,
                                         unsigned one, unsigned m13, unsigned m15) {
    unsigned base = blk * BWORK;
    #pragma unroll
    for (unsigned k = 0; k < 32; k += 4) {
        unsigned i0 = base + (k << 8) + t;
        unsigned o0, o1, o2, o3;
        tf_bits4(i0, i0 + 256u, i0 + 512u, i0 + 768u, o0, o1, o2, o3, one, m13, m15);
        g_bits[i0]        = o0;
        g_bits[i0 + 256u] = o1;
        g_bits[i0 + 512u] = o2;
        g_bits[i0 + 768u] = o3;
    }
}

/* ============ K1: bits chunk 1  ||  zero grid (fat blocks)  ||  tables ============ */
__global__ void __launch_bounds__(256) k_f1(unsigned one) {
    unsigned b = blockIdx.x, t = threadIdx.x;
    if (b < PB1) {
        if (b == 0) {
            if (t < 36) {
                float tp  = 6.28318530717958647692f;     /* rounds to f32(2pi) */
                float r36 = __fdiv_rn(1.0f, 36.0f);
                float th  = __fmul_rn(__fmul_rn(tp, (float)t), r36);
                g_cs[2*t]   = cosf(th);
                g_cs[2*t+1] = sinf(th);
            }
            if (t == 0) g_D = 0.0f;
        }
        bits_job(b, t, one, one << 13, one << 15);
    } else {
        unsigned zb = b - PB1;                  /* < ZFAT; 4096 float4s per block */
        float4 z4 = make_float4(0.f, 0.f, 0.f, 0.f);
        unsigned base = zb * 4096u + t;
        #pragma unroll
        for (unsigned k = 0; k < 16; k++)
            g_grid4[base + k * 256u] = z4;
    }
}

/* ============ K2: Hough vote scatter (v4 red)  ||  bits chunk 2 ============ */
__global__ void __launch_bounds__(256) k_f2(const float* __restrict__ pc,
                                            const float* __restrict__ xyz,
                                            const float* __restrict__ scale,
                                            const float* __restrict__ prob,
                                            const float* __restrict__ corners,
                                            int N, int vb, unsigned one) {
    unsigned b = blockIdx.x, t = threadIdx.x;
    if (b >= (unsigned)vb) { bits_job(PB1 + (b - vb), t, one, one << 13, one << 15); return; }

    int i = (int)b * 256 + (int)t;
    if (i >= N) return;
    const float RCP = __fdiv_rn(1.0f, RESF);
    float px = pc[3*i], py = pc[3*i+1], pz = pc[3*i+2];
    float ox = xyz[3*i], oy = xyz[3*i+1], oz = xyz[3*i+2];
    float w  = prob[i];
    float c0x = corners[0], c0y = corners[1], c0z = corners[2];

    float ty = __fadd_rn(py, oy);
    float fy = __fadd_rn(__fmul_rn(__fsub_rn(ty, c0y), RCP), 0.5f);
    int iy = (int)floorf(fy);
    if (iy < 0 || iy >= GY) return;          /* zero weight for all rots */

    float wsx = __fmul_rn(w, scale[3*i]);
    float wsy = __fmul_rn(w, scale[3*i+1]);
    float wsz = __fmul_rn(w, scale[3*i+2]);

    #pragma unroll 4
    for (int r = 0; r < 36; r++) {
        float cth = g_cs[2*r], sth = g_cs[2*r+1];
        float rx = __fadd_rn(__fmul_rn(ox, cth), __fmul_rn(oz, sth));
        float rz = __fadd_rn(-__fmul_rn(ox, sth), __fmul_rn(oz, cth));
        float tx = __fadd_rn(px, rx);
        float tz = __fadd_rn(pz, rz);
        int ix = (int)floorf(__fadd_rn(__fmul_rn(__fsub_rn(tx, c0x), RCP), 0.5f));
        int iz = (int)floorf(__fadd_rn(__fmul_rn(__fsub_rn(tz, c0z), RCP), 0.5f));
        if (ix >= 0 && ix < GX && iz >= 0 && iz < GZ) {
            unsigned cell = ((unsigned)(ix*GY + iy))*GZ + (unsigned)iz;
            asm volatile("red.global.add.v4.f32 [%0], {%1, %2, %3, %4};"
                         :: "l"(&g_grid4[cell]), "f"(w), "f"(wsx), "f"(wsy), "f"(wsz)
                         : "memory");
        }
    }
}

/* ============ K3: colmax + dist + sum(dist)  ||  bits chunk 3 ============ */
__global__ void __launch_bounds__(256) k_f3(unsigned one) {
    __shared__ float sh[256];
    unsigned b = blockIdx.x, t = threadIdx.x;
    if (b >= CMBLKS) { bits_job(PB1 + PB2 + (b - CMBLKS), t, one, one << 13, one << 15); return; }

    unsigned cell = b * 256u + t;                  /* < NC2 exactly */
    unsigned x = cell / GZ, z = cell - x * GZ;
    const float4* col = g_grid4 + (size_t)x * GY * GZ + z;
    float m = col[0].x; int my = 0;
    #pragma unroll 8
    for (int y = 1; y < GY; y++) {
        float v = col[(size_t)y * GZ].x;
        if (v > m) { m = v; my = y; }              /* first index on ties */
    }
    float d = sqrtf(__fadd_rn(m, 1e-7f));          /* XLA pow(x,.5)->sqrt */
    g_dist[cell] = d;
    g_yidx[cell] = my;

    /* block partial sum of dist -> g_D (feeds only the conservative filter) */
    sh[t] = d; __syncthreads();
    for (int o = 128; o > 0; o >>= 1) {
        if (t < (unsigned)o) sh[t] += sh[t + o];
        __syncthreads();
    }
    if (t == 0) atomicAdd(&g_D, sh[0]);
}

/* ============ K4: log(dist) + raw-bits pass threshold (f32) ============
   element can only beat s_T = D/50 if u > T = exp(-50*d_c/D).
   margin 512 mantissa units >> __expf error.                          */
__global__ void __launch_bounds__(256) k_bth() {
    unsigned c = blockIdx.x * 256u + threadIdx.x;
    if (c >= NC2) return;
    float d = g_dist[c];
    g_logd[c] = logf(__fadd_rn(d, 1e-30f));
    float T = __expf(-50.0f * d / g_D);
    int Mi = (int)floorf(T * 8388608.0f) - 512;
    if (Mi < 0) Mi = 0;
    g_bth[c] = ((unsigned)Mi) << 9;
}

/* ============ K5: per-row select + gather + seed dist ============ */
__device__ __forceinline__ void sel_try(unsigned b, unsigned th, int c,
                                        float& bs, int& bi) {
    if (b >= th) {
        unsigned m = b >> 9;
        float u = (m == 0u) ? 1.17549435e-38f
                            : __fadd_rn(__uint_as_float(m | 0x3f800000u), -1.0f);
        float g = -logf(-logf(u));                 /* exact ref gumbel */
        float s = __fadd_rn(g_logd[c], g);
        if (s > bs) { bs = s; bi = c; }
    }
}

__global__ void __launch_bounds__(256, 7) k_sel(const float* __restrict__ corners,
                                                const float* __restrict__ vp, int M,
                                                unsigned one) {
    __shared__ float ss[256];
    __shared__ int   si[256];
    __shared__ float sw[3];
    int r = blockIdx.x, tid = threadIdx.x;
    float bs = -3.4e38f; int bi = 0;
    const uint4* thv = reinterpret_cast<const uint4*>(g_bth);

    if (r < (int)RPRE) {
        /* precomputed rows: stream bits from DRAM, vectorized */
        const uint4* rowb = reinterpret_cast<const uint4*>(g_bits + (size_t)r * NC2);
        for (unsigned q = tid; q < NC2/4u; q += 256u) {
            uint4 v  = rowb[q];
            uint4 th = thv[q];
            int c = (int)(q * 4u);
            sel_try(v.x, th.x, c,   bs, bi);
            sel_try(v.y, th.y, c+1, bs, bi);
            sel_try(v.z, th.z, c+2, bs, bi);
            sel_try(v.w, th.w, c+3, bs, bi);
        }
    } else {
        /* inline threefry rows: 4 counters per iteration (ILP) */
        unsigned m13 = one << 13, m15 = one << 15;
        unsigned base = (unsigned)r * NC2;
        for (unsigned q = tid; q < NC2/4u; q += 256u) {
            unsigned j = base + q * 4u;
            unsigned o0, o1, o2, o3;
            tf_bits4(j, j+1u, j+2u, j+3u, o0, o1, o2, o3, one, m13, m15);
            uint4 th = thv[q];
            int c = (int)(q * 4u);
            sel_try(o0, th.x, c,   bs, bi);
            sel_try(o1, th.y, c+1, bs, bi);
            sel_try(o2, th.z, c+2, bs, bi);
            sel_try(o3, th.w, c+3, bs, bi);
        }
    }

    ss[tid] = bs; si[tid] = bi; __syncthreads();
    for (int o = 128; o > 0; o >>= 1) {
        if (tid < o) {
            float s2 = ss[tid+o]; int i2 = si[tid+o];
            if (s2 > ss[tid] || (s2 == ss[tid] && i2 < si[tid])) { ss[tid] = s2; si[tid] = i2; }
        }
        __syncthreads();
    }

    if (tid == 0) {
        int c  = si[0];
        int xi = c / GZ, zi = c - (c / GZ) * GZ;
        int yi = g_yidx[c];
        float wx = __fadd_rn(__fmul_rn((float)xi, RESF), corners[0]);
        float wy = __fadd_rn(__fmul_rn((float)yi, RESF), corners[1]);
        float wz = __fadd_rn(__fmul_rn((float)zi, RESF), corners[2]);
        g_world[3*r+0] = wx; g_world[3*r+1] = wy; g_world[3*r+2] = wz;
        sw[0] = wx; sw[1] = wy; sw[2] = wz;
        unsigned cell = ((unsigned)(xi*GY + yi))*GZ + (unsigned)zi;
        float4 gv = g_grid4[cell];
        float den = __fadd_rn(gv.x, 1e-7f);
        g_scout[3*r+0] = __fdiv_rn(gv.y, den);
        g_scout[3*r+1] = __fdiv_rn(gv.z, den);
        g_scout[3*r+2] = __fdiv_rn(gv.w, den);
    }
    __syncthreads();

    /* min distance to seed points for this row (full 256-thread fold) */
    float wx = sw[0], wy = sw[1], wz = sw[2];
    float mind = 3.4e38f;
    for (int m = tid; m < M; m += 256) {
        float dx = __fsub_rn(wx, vp[3*m]);
        float dy = __fsub_rn(wy, vp[3*m+1]);
        float dz = __fsub_rn(wz, vp[3*m+2]);
        float s  = __fadd_rn(__fadd_rn(__fmul_rn(dx,dx), __fmul_rn(dy,dy)), __fmul_rn(dz,dz));
        mind = fminf(mind, sqrtf(s));
    }
    ss[tid] = mind; __syncthreads();
    for (int o = 128; o > 0; o >>= 1) {
        if (tid < o) ss[tid] = fminf(ss[tid], ss[tid+o]);
        __syncthreads();
    }
    if (tid == 0) g_keep[r] = (ss[0] < 0.3f) ? 1 : 0;
}

/* ============ K6: parallel stable selection + output write ============ */
__global__ void __launch_bounds__(1024) k_finish(float* __restrict__ out) {
    __shared__ int sk[NROWS];
    int t = threadIdx.x;                       /* 1024 threads, one per row */
    int kp = g_keep[t];
    sk[t] = kp; __syncthreads();

    /* inclusive prefix sum of keep flags (Hillis-Steele) */
    for (int o = 1; o < NROWS; o <<= 1) {
        int val = sk[t];
        if (t >= o) val += sk[t - o];
        __syncthreads();
        sk[t] = val;
        __syncthreads();
    }
    int incl  = sk[t];
    int total = sk[NROWS - 1];

    /* output slot for this row under stable argsort(where(keep,0,1)) */
    int slot;
    if (total > 0) slot = kp ? (incl - 1) : (total + (t - incl));
    else           slot = t;                   /* keep.any()==False -> identity */

    if (slot < NPROP) {
        out[3*slot+0] = g_world[3*t+0];
        out[3*slot+1] = g_world[3*t+1];
        out[3*slot+2] = g_world[3*t+2];
        out[4*NPROP + 3*slot+0] = g_scout[3*t+0];
        out[4*NPROP + 3*slot+1] = g_scout[3*t+1];
        out[4*NPROP + 3*slot+2] = g_scout[3*t+2];
    }
    if (t < NPROP) out[3*NPROP + t] = 0.0f;    /* probs = zeros */
}

extern "C" void kernel_launch(void* const* d_in, const int* in_sizes, int n_in,
                              void* d_out, int out_size) {
    const float* pc      = (const float*)d_in[0];
    const float* xyz     = (const float*)d_in[1];
    const float* scale   = (const float*)d_in[2];
    const float* prob    = (const float*)d_in[3];
    const float* corners = (const float*)d_in[4];
    const float* vp      = (const float*)d_in[5];
    int N = in_sizes[0] / 3;
    int M = in_sizes[5] / 3;
    float* out = (float*)d_out;
    int vb = (N + 255) / 256;
    unsigned one = 1u;                          /* opaque to ptxas: pipe-balancing anchor */

    k_f1<<<PB1 + ZFAT, 256>>>(one);
    k_f2<<<vb + PB2, 256>>>(pc, xyz, scale, prob, corners, N, vb, one);
    k_f3<<<CMBLKS + PB3, 256>>>(one);
    k_bth<<<CMBLKS, 256>>>();
    k_sel<<<NROWS, 256>>>(corners, vp, M, one);
    k_finish<<<1, 1024>>>(out);
}

// round 17
// speedup vs baseline: 1.0866x; 1.0057x over previous
#include <cuda_runtime.h>
#include <math.h>
#include <stdint.h>

#define GX 272
#define GY 112
#define GZ 272
#define NCELL 8286208u            /* GX*GY*GZ */
#define NC2   73984u              /* GX*GZ = 289*256 */
#define NROWS 1024
#define NPROP 256
#define RESF  0.03f

#define RPRE  768u                /* rows with precomputed bits */
#define NPREW (RPRE*NC2)          /* 56,819,712 = 8192*6936 */
#define BWORK 8192u               /* counters per bits-block (256 thr * 32) */
#define PB1   1200u               /* bits blocks fused into K1 */
#define PB2   4712u               /* bits blocks fused into K2 */
#define PB3   1024u               /* bits blocks fused into K3 (sum = 6936) */
#define ZFAT  2023u               /* fat zero blocks: 2023*4096 float4 = NCELL */
#define CMBLKS 289u               /* NC2/256 */

/* ------------- static device scratch (no allocations) ------------- */
__device__ float4   g_grid4[NCELL];      /* 132 MB: (obj, sx, sy, sz) per cell */
__device__ unsigned g_bits[NPREW];       /* 227 MB: precomputed RNG rows 0..767 */
__device__ float    g_cs[72];
__device__ float    g_dist[NC2];
__device__ float    g_logd[NC2];
__device__ int      g_yidx[NC2];
__device__ unsigned g_bth[NC2];
__device__ float    g_D;
__device__ float    g_world[NROWS*3];
__device__ float    g_scout[NROWS*3];
__device__ int      g_keep[NROWS];

/* ---- pipe-balancing add: IMAD on fma pipe; `one`==1 is a kernel param
   so ptxas cannot strength-reduce it back to IADD3 (alu pipe). Exact. ---- */
__device__ __forceinline__ unsigned addv(unsigned a, unsigned b, unsigned one) {
    unsigned r;
    asm("mad.lo.u32 %0, %1, %2, %3;" : "=r"(r) : "r"(a), "r"(one), "r"(b));
    return r;
}
template<unsigned K>
__device__ __forceinline__ unsigned addk(unsigned a, unsigned one) {
    if constexpr (K == 0u) { return a; }
    else {
        unsigned r;
        asm("mad.lo.u32 %0, %1, %2, %3;" : "=r"(r) : "n"(K), "r"(one), "r"(a));
        return r;
    }
}
/* wide-mul rotate on the fma pipe: rotl(x,r) = lo(x*2^r) | hi(x*2^r);
   the OR fuses with the round xor into one LOP3: (lo|hi)^x0.
   NOTE (round-13 lesson): at most 6 of these per eval — more overloads
   the fma pipe / register budget and regresses.                       */
__device__ __forceinline__ unsigned wrotx(unsigned x, unsigned m, unsigned x0) {
    unsigned long long y = (unsigned long long)x * m;
    return (((unsigned)y) | ((unsigned)(y >> 32))) ^ x0;
}

/* ------------- Threefry-2x32, key=(0,42) -------------
   parity = 0x1BD11BDA  =>  ks2 = 0x1BD11BDA ^ 42 = 0x1BD11BF0
   partitionable mode: ctr = (hi=0, lo=j); 32-bit out = bits1 ^ bits2
   *** verified bit-exact rounds 6-16 — integer identities only ***    */

/* ---- generic round/injection steps over one chain ---- */
__device__ __forceinline__ void tfr_s(unsigned& x0, unsigned& x1, int r, unsigned one) {
    x0 = addv(x0, x1, one);
    x1 = __funnelshift_l(x1, x1, r) ^ x0;
}
__device__ __forceinline__ void tfr_w(unsigned& x0, unsigned& x1, unsigned m, unsigned one) {
    x0 = addv(x0, x1, one);
    x1 = wrotx(x1, m, x0);
}

/* full 20-round schedule on one chain (used via multi-chain interleave
   below; compiler interleaves independent chains for ILP) */
template<int NCH>
__device__ __forceinline__ void tf_batch(const unsigned* j, unsigned* o,
                                         unsigned one, unsigned m13, unsigned m15) {
    unsigned x0[NCH], x1[NCH];
    #pragma unroll
    for (int i = 0; i < NCH; i++) { x1[i] = addk<42u>(j[i], one); }
    /* G1: first round has x0==0 -> copy; rot13/rot15 in wide form */
    #pragma unroll
    for (int i = 0; i < NCH; i++) { x0[i] = x1[i]; x1[i] = wrotx(x1[i], m13, x0[i]); }
    #pragma unroll
    for (int i = 0; i < NCH; i++) tfr_w(x0[i], x1[i], m15, one);
    #pragma unroll
    for (int i = 0; i < NCH; i++) tfr_s(x0[i], x1[i], 26, one);
    #pragma unroll
    for (int i = 0; i < NCH; i++) tfr_s(x0[i], x1[i], 6, one);
    #pragma unroll
    for (int i = 0; i < NCH; i++) { x0[i] = addk<42u>(x0[i], one); x1[i] = addk<0x1BD11BF1u>(x1[i], one); }
    #pragma unroll
    for (int i = 0; i < NCH; i++) tfr_s(x0[i], x1[i], 17, one);
    #pragma unroll
    for (int i = 0; i < NCH; i++) tfr_s(x0[i], x1[i], 29, one);
    #pragma unroll
    for (int i = 0; i < NCH; i++) tfr_s(x0[i], x1[i], 16, one);
    #pragma unroll
    for (int i = 0; i < NCH; i++) tfr_s(x0[i], x1[i], 24, one);
    #pragma unroll
    for (int i = 0; i < NCH; i++) { x0[i] = addk<0x1BD11BF0u>(x0[i], one); x1[i] = addk<2u>(x1[i], one); }
    #pragma unroll
    for (int i = 0; i < NCH; i++) tfr_w(x0[i], x1[i], m13, one);
    #pragma unroll
    for (int i = 0; i < NCH; i++) tfr_w(x0[i], x1[i], m15, one);
    #pragma unroll
    for (int i = 0; i < NCH; i++) tfr_s(x0[i], x1[i], 26, one);
    #pragma unroll
    for (int i = 0; i < NCH; i++) tfr_s(x0[i], x1[i], 6, one);
    #pragma unroll
    for (int i = 0; i < NCH; i++) { x1[i] = addk<45u>(x1[i], one); }
    #pragma unroll
    for (int i = 0; i < NCH; i++) tfr_s(x0[i], x1[i], 17, one);
    #pragma unroll
    for (int i = 0; i < NCH; i++) tfr_s(x0[i], x1[i], 29, one);
    #pragma unroll
    for (int i = 0; i < NCH; i++) tfr_s(x0[i], x1[i], 16, one);
    #pragma unroll
    for (int i = 0; i < NCH; i++) tfr_s(x0[i], x1[i], 24, one);
    #pragma unroll
    for (int i = 0; i < NCH; i++) { x0[i] = addk<42u>(x0[i], one); x1[i] = addk<0x1BD11BF4u>(x1[i], one); }
    #pragma unroll
    for (int i = 0; i < NCH; i++) tfr_w(x0[i], x1[i], m13, one);
    #pragma unroll
    for (int i = 0; i < NCH; i++) tfr_w(x0[i], x1[i], m15, one);
    #pragma unroll
    for (int i = 0; i < NCH; i++) tfr_s(x0[i], x1[i], 26, one);
    #pragma unroll
    for (int i = 0; i < NCH; i++) tfr_s(x0[i], x1[i], 6, one);
    #pragma unroll
    for (int i = 0; i < NCH; i++) { x0[i] = addk<0x1BD11BF0u>(x0[i], one); x1[i] = addk<5u>(x1[i], one); }
    #pragma unroll
    for (int i = 0; i < NCH; i++) o[i] = x0[i] ^ x1[i];
}

__device__ __forceinline__ void tf_bits4(unsigned j0, unsigned j1, unsigned j2, unsigned j3,
                                         unsigned& o0, unsigned& o1, unsigned& o2, unsigned& o3,
                                         unsigned one, unsigned m13, unsigned m15) {
    unsigned j[4] = { j0, j1, j2, j3 };
    unsigned o[4];
    tf_batch<4>(j, o, one, m13, m15);
    o0 = o[0]; o1 = o[1]; o2 = o[2]; o3 = o[3];
}

/* bits block: 256 threads produce 8192 consecutive counters, coalesced.
   8-way ILP (phases only — no occupancy cap here).                    */
__device__ __forceinline__ void bits_job(unsigned blk, unsigned t,
                                         unsigned one, unsigned m13, unsigned m15) {
    unsigned base = blk * BWORK;
    #pragma unroll
    for (unsigned k = 0; k < 32; k += 8) {
        unsigned i0 = base + (k << 8) + t;
        unsigned j[8], o[8];
        #pragma unroll
        for (int i = 0; i < 8; i++) j[i] = i0 + (unsigned)i * 256u;
        tf_batch<8>(j, o, one, m13, m15);
        #pragma unroll
        for (int i = 0; i < 8; i++) g_bits[i0 + (unsigned)i * 256u] = o[i];
    }
}

/* ============ K1: bits chunk 1  ||  zero grid (fat blocks)  ||  tables ============ */
__global__ void __launch_bounds__(256) k_f1(unsigned one) {
    unsigned b = blockIdx.x, t = threadIdx.x;
    if (b < PB1) {
        if (b == 0) {
            if (t < 36) {
                float tp  = 6.28318530717958647692f;     /* rounds to f32(2pi) */
                float r36 = __fdiv_rn(1.0f, 36.0f);
                float th  = __fmul_rn(__fmul_rn(tp, (float)t), r36);
                g_cs[2*t]   = cosf(th);
                g_cs[2*t+1] = sinf(th);
            }
            if (t == 0) g_D = 0.0f;
        }
        bits_job(b, t, one, one << 13, one << 15);
    } else {
        unsigned zb = b - PB1;                  /* < ZFAT; 4096 float4s per block */
        float4 z4 = make_float4(0.f, 0.f, 0.f, 0.f);
        unsigned base = zb * 4096u + t;
        #pragma unroll
        for (unsigned k = 0; k < 16; k++)
            g_grid4[base + k * 256u] = z4;
    }
}

/* ============ K2: Hough vote scatter (v4 red)  ||  bits chunk 2 ============ */
__global__ void __launch_bounds__(256) k_f2(const float* __restrict__ pc,
                                            const float* __restrict__ xyz,
                                            const float* __restrict__ scale,
                                            const float* __restrict__ prob,
                                            const float* __restrict__ corners,
                                            int N, int vb, unsigned one) {
    unsigned b = blockIdx.x, t = threadIdx.x;
    if (b >= (unsigned)vb) { bits_job(PB1 + (b - vb), t, one, one << 13, one << 15); return; }

    int i = (int)b * 256 + (int)t;
    if (i >= N) return;
    const float RCP = __fdiv_rn(1.0f, RESF);
    float px = pc[3*i], py = pc[3*i+1], pz = pc[3*i+2];
    float ox = xyz[3*i], oy = xyz[3*i+1], oz = xyz[3*i+2];
    float w  = prob[i];
    float c0x = corners[0], c0y = corners[1], c0z = corners[2];

    float ty = __fadd_rn(py, oy);
    float fy = __fadd_rn(__fmul_rn(__fsub_rn(ty, c0y), RCP), 0.5f);
    int iy = (int)floorf(fy);
    if (iy < 0 || iy >= GY) return;          /* zero weight for all rots */

    float wsx = __fmul_rn(w, scale[3*i]);
    float wsy = __fmul_rn(w, scale[3*i+1]);
    float wsz = __fmul_rn(w, scale[3*i+2]);

    #pragma unroll 4
    for (int r = 0; r < 36; r++) {
        float cth = g_cs[2*r], sth = g_cs[2*r+1];
        float rx = __fadd_rn(__fmul_rn(ox, cth), __fmul_rn(oz, sth));
        float rz = __fadd_rn(-__fmul_rn(ox, sth), __fmul_rn(oz, cth));
        float tx = __fadd_rn(px, rx);
        float tz = __fadd_rn(pz, rz);
        int ix = (int)floorf(__fadd_rn(__fmul_rn(__fsub_rn(tx, c0x), RCP), 0.5f));
        int iz = (int)floorf(__fadd_rn(__fmul_rn(__fsub_rn(tz, c0z), RCP), 0.5f));
        if (ix >= 0 && ix < GX && iz >= 0 && iz < GZ) {
            unsigned cell = ((unsigned)(ix*GY + iy))*GZ + (unsigned)iz;
            asm volatile("red.global.add.v4.f32 [%0], {%1, %2, %3, %4};"
                         :: "l"(&g_grid4[cell]), "f"(w), "f"(wsx), "f"(wsy), "f"(wsz)
                         : "memory");
        }
    }
}

/* ============ K3: colmax + dist + sum(dist)  ||  bits chunk 3 ============ */
__global__ void __launch_bounds__(256) k_f3(unsigned one) {
    __shared__ float sh[256];
    unsigned b = blockIdx.x, t = threadIdx.x;
    if (b >= CMBLKS) { bits_job(PB1 + PB2 + (b - CMBLKS), t, one, one << 13, one << 15); return; }

    unsigned cell = b * 256u + t;                  /* < NC2 exactly */
    unsigned x = cell / GZ, z = cell - x * GZ;
    const float4* col = g_grid4 + (size_t)x * GY * GZ + z;
    float m = col[0].x; int my = 0;
    #pragma unroll 8
    for (int y = 1; y < GY; y++) {
        float v = col[(size_t)y * GZ].x;
        if (v > m) { m = v; my = y; }              /* first index on ties */
    }
    float d = sqrtf(__fadd_rn(m, 1e-7f));          /* XLA pow(x,.5)->sqrt */
    g_dist[cell] = d;
    g_yidx[cell] = my;

    /* block partial sum of dist -> g_D (feeds only the conservative filter) */
    sh[t] = d; __syncthreads();
    for (int o = 128; o > 0; o >>= 1) {
        if (t < (unsigned)o) sh[t] += sh[t + o];
        __syncthreads();
    }
    if (t == 0) atomicAdd(&g_D, sh[0]);
}

/* ============ K4: log(dist) + raw-bits pass threshold (f32) ============
   element can only beat s_T = D/50 if u > T = exp(-50*d_c/D).
   margin 512 mantissa units >> __expf error.                          */
__global__ void __launch_bounds__(256) k_bth() {
    unsigned c = blockIdx.x * 256u + threadIdx.x;
    if (c >= NC2) return;
    float d = g_dist[c];
    g_logd[c] = logf(__fadd_rn(d, 1e-30f));
    float T = __expf(-50.0f * d / g_D);
    int Mi = (int)floorf(T * 8388608.0f) - 512;
    if (Mi < 0) Mi = 0;
    g_bth[c] = ((unsigned)Mi) << 9;
}

/* ============ K5: per-row select + gather + seed dist ============ */
__device__ __forceinline__ void sel_try(unsigned b, unsigned th, int c,
                                        float& bs, int& bi) {
    if (b >= th) {
        unsigned m = b >> 9;
        float u = (m == 0u) ? 1.17549435e-38f
                            : __fadd_rn(__uint_as_float(m | 0x3f800000u), -1.0f);
        float g = -logf(-logf(u));                 /* exact ref gumbel */
        float s = __fadd_rn(g_logd[c], g);
        if (s > bs) { bs = s; bi = c; }
    }
}

__global__ void __launch_bounds__(256, 7) k_sel(const float* __restrict__ corners,
                                                const float* __restrict__ vp, int M,
                                                unsigned one) {
    __shared__ float ss[256];
    __shared__ int   si[256];
    __shared__ float sw[3];
    int r = blockIdx.x, tid = threadIdx.x;
    float bs = -3.4e38f; int bi = 0;
    const uint4* thv = reinterpret_cast<const uint4*>(g_bth);

    if (r < (int)RPRE) {
        /* precomputed rows: stream bits from DRAM, vectorized */
        const uint4* rowb = reinterpret_cast<const uint4*>(g_bits + (size_t)r * NC2);
        for (unsigned q = tid; q < NC2/4u; q += 256u) {
            uint4 v  = rowb[q];
            uint4 th = thv[q];
            int c = (int)(q * 4u);
            sel_try(v.x, th.x, c,   bs, bi);
            sel_try(v.y, th.y, c+1, bs, bi);
            sel_try(v.z, th.z, c+2, bs, bi);
            sel_try(v.w, th.w, c+3, bs, bi);
        }
    } else {
        /* inline threefry rows: 4 counters per iteration (reg-capped) */
        unsigned m13 = one << 13, m15 = one << 15;
        unsigned base = (unsigned)r * NC2;
        for (unsigned q = tid; q < NC2/4u; q += 256u) {
            unsigned j = base + q * 4u;
            unsigned o0, o1, o2, o3;
            tf_bits4(j, j+1u, j+2u, j+3u, o0, o1, o2, o3, one, m13, m15);
            uint4 th = thv[q];
            int c = (int)(q * 4u);
            sel_try(o0, th.x, c,   bs, bi);
            sel_try(o1, th.y, c+1, bs, bi);
            sel_try(o2, th.z, c+2, bs, bi);
            sel_try(o3, th.w, c+3, bs, bi);
        }
    }

    ss[tid] = bs; si[tid] = bi; __syncthreads();
    for (int o = 128; o > 0; o >>= 1) {
        if (tid < o) {
            float s2 = ss[tid+o]; int i2 = si[tid+o];
            if (s2 > ss[tid] || (s2 == ss[tid] && i2 < si[tid])) { ss[tid] = s2; si[tid] = i2; }
        }
        __syncthreads();
    }

    if (tid == 0) {
        int c  = si[0];
        int xi = c / GZ, zi = c - (c / GZ) * GZ;
        int yi = g_yidx[c];
        float wx = __fadd_rn(__fmul_rn((float)xi, RESF), corners[0]);
        float wy = __fadd_rn(__fmul_rn((float)yi, RESF), corners[1]);
        float wz = __fadd_rn(__fmul_rn((float)zi, RESF), corners[2]);
        g_world[3*r+0] = wx; g_world[3*r+1] = wy; g_world[3*r+2] = wz;
        sw[0] = wx; sw[1] = wy; sw[2] = wz;
        unsigned cell = ((unsigned)(xi*GY + yi))*GZ + (unsigned)zi;
        float4 gv = g_grid4[cell];
        float den = __fadd_rn(gv.x, 1e-7f);
        g_scout[3*r+0] = __fdiv_rn(gv.y, den);
        g_scout[3*r+1] = __fdiv_rn(gv.z, den);
        g_scout[3*r+2] = __fdiv_rn(gv.w, den);
    }
    __syncthreads();

    /* min distance to seed points for this row (full 256-thread fold) */
    float wx = sw[0], wy = sw[1], wz = sw[2];
    float mind = 3.4e38f;
    for (int m = tid; m < M; m += 256) {
        float dx = __fsub_rn(wx, vp[3*m]);
        float dy = __fsub_rn(wy, vp[3*m+1]);
        float dz = __fsub_rn(wz, vp[3*m+2]);
        float s  = __fadd_rn(__fadd_rn(__fmul_rn(dx,dx), __fmul_rn(dy,dy)), __fmul_rn(dz,dz));
        mind = fminf(mind, sqrtf(s));
    }
    ss[tid] = mind; __syncthreads();
    for (int o = 128; o > 0; o >>= 1) {
        if (tid < o) ss[tid] = fminf(ss[tid], ss[tid+o]);
        __syncthreads();
    }
    if (tid == 0) g_keep[r] = (ss[0] < 0.3f) ? 1 : 0;
}

/* ============ K6: parallel stable selection + output write ============ */
__global__ void __launch_bounds__(1024) k_finish(float* __restrict__ out) {
    __shared__ int sk[NROWS];
    int t = threadIdx.x;                       /* 1024 threads, one per row */
    int kp = g_keep[t];
    sk[t] = kp; __syncthreads();

    /* inclusive prefix sum of keep flags (Hillis-Steele) */
    for (int o = 1; o < NROWS; o <<= 1) {
        int val = sk[t];
        if (t >= o) val += sk[t - o];
        __syncthreads();
        sk[t] = val;
        __syncthreads();
    }
    int incl  = sk[t];
    int total = sk[NROWS - 1];

    /* output slot for this row under stable argsort(where(keep,0,1)) */
    int slot;
    if (total > 0) slot = kp ? (incl - 1) : (total + (t - incl));
    else           slot = t;                   /* keep.any()==False -> identity */

    if (slot < NPROP) {
        out[3*slot+0] = g_world[3*t+0];
        out[3*slot+1] = g_world[3*t+1];
        out[3*slot+2] = g_world[3*t+2];
        out[4*NPROP + 3*slot+0] = g_scout[3*t+0];
        out[4*NPROP + 3*slot+1] = g_scout[3*t+1];
        out[4*NPROP + 3*slot+2] = g_scout[3*t+2];
    }
    if (t < NPROP) out[3*NPROP + t] = 0.0f;    /* probs = zeros */
}

extern "C" void kernel_launch(void* const* d_in, const int* in_sizes, int n_in,
                              void* d_out, int out_size) {
    const float* pc      = (const float*)d_in[0];
    const float* xyz     = (const float*)d_in[1];
    const float* scale   = (const float*)d_in[2];
    const float* prob    = (const float*)d_in[3];
    const float* corners = (const float*)d_in[4];
    const float* vp      = (const float*)d_in[5];
    int N = in_sizes[0] / 3;
    int M = in_sizes[5] / 3;
    float* out = (float*)d_out;
    int vb = (N + 255) / 256;
    unsigned one = 1u;                          /* opaque to ptxas: pipe-balancing anchor */

    k_f1<<<PB1 + ZFAT, 256>>>(one);
    k_f2<<<vb + PB2, 256>>>(pc, xyz, scale, prob, corners, N, vb, one);
    k_f3<<<CMBLKS + PB3, 256>>>(one);
    k_bth<<<CMBLKS, 256>>>();
    k_sel<<<NROWS, 256>>>(corners, vp, M, one);
    k_finish<<<1, 1024>>>(out);
}